// round 6
// baseline (speedup 1.0000x reference)
#include <cuda_runtime.h>
#include <cstddef>

#define BATCH 4
#define CIN   48
#define C6    288
#define C2    96
#define HH    256
#define WW    256
#define ST    68   // padded smem row stride (floats) for K2 tiles

// 302 MB scratch for qkv = dw3x3(conv1x1(x)); q=[0,96), k=[96,192), v=[192,288)
__device__ float g_qkv[(size_t)BATCH * C6 * HH * WW];

// ---------------------------------------------------------------------------
// K1: fused 1x1 conv (48->288, bias) + depthwise 3x3 SAME (bias) -> g_qkv
// grid (16,16,B), block 352, 2 CTAs/SM. 4 output channels per iteration.
// Conv phase: 1 LDS.128 per 4 FFMA (weights), x register-resident.
// ---------------------------------------------------------------------------
__global__ void __launch_bounds__(352, 2)
fsas_k1(const float* __restrict__ x,
        const float* __restrict__ w1,
        const float* __restrict__ b1,
        const float* __restrict__ wdw,
        const float* __restrict__ bdw) {
    extern __shared__ float sm1[];
    float* w1s  = sm1;               // C6*CIN = 13824
    float* wdws = w1s + C6 * CIN;    // C6*9   = 2592
    float* b1s  = wdws + C6 * 9;     // 288
    float* bdws = b1s + C6;          // 288
    float* hid  = bdws + C6;         // 4*324  = 1296

    const int tid = threadIdx.x;
    const int b  = blockIdx.z;
    const int h0 = blockIdx.y * 16;
    const int w0 = blockIdx.x * 16;

    for (int i = tid; i < C6 * CIN; i += blockDim.x) w1s[i] = w1[i];
    for (int i = tid; i < C6 * 9;   i += blockDim.x) wdws[i] = wdw[i];
    for (int i = tid; i < C6;       i += blockDim.x) { b1s[i] = b1[i]; bdws[i] = bdw[i]; }

    // each thread owns one halo pixel (18x18 = 324) and register-caches x[ch]
    const int s  = tid;
    const int ty = s / 18, tx = s % 18;
    const int hh = h0 - 1 + ty;
    const int ww = w0 - 1 + tx;
    const bool inimg = (s < 324) && hh >= 0 && hh < HH && ww >= 0 && ww < WW;

    float xr[CIN];
    if (inimg) {
        const float* xp = x + ((size_t)b * CIN) * HH * WW + (size_t)hh * WW + ww;
        #pragma unroll
        for (int c = 0; c < CIN; c++) xr[c] = xp[(size_t)c * HH * WW];
    } else {
        #pragma unroll
        for (int c = 0; c < CIN; c++) xr[c] = 0.0f;
    }

    __syncthreads();

    for (int o = 0; o < C6; o += 4) {
        if (s < 324) {
            float a0[4] = {0.f, 0.f, 0.f, 0.f};
            float a1[4] = {0.f, 0.f, 0.f, 0.f};
            float a2[4] = {0.f, 0.f, 0.f, 0.f};
            float a3[4] = {0.f, 0.f, 0.f, 0.f};
            #pragma unroll
            for (int c = 0; c < CIN; c += 4) {
                #pragma unroll
                for (int q = 0; q < 4; q++) {
                    const float4 w4 = *(const float4*)&w1s[(o + q) * CIN + c];
                    a0[q] += w4.x * xr[c + 0];
                    a1[q] += w4.y * xr[c + 1];
                    a2[q] += w4.z * xr[c + 2];
                    a3[q] += w4.w * xr[c + 3];
                }
            }
            #pragma unroll
            for (int q = 0; q < 4; q++)
                hid[q * 324 + s] = inimg
                    ? ((a0[q] + a1[q]) + (a2[q] + a3[q]) + b1s[o + q]) : 0.0f;
        }
        __syncthreads();
        // depthwise 3x3 over 4 channels x 256 pixels, all 352 threads
        for (int u = tid; u < 1024; u += 352) {
            const int q   = u >> 8;
            const int pix = u & 255;
            const int py  = pix >> 4, px = pix & 15;
            const float* wd = &wdws[(o + q) * 9];
            const float* hb = &hid[q * 324];
            float acc = bdws[o + q];
            #pragma unroll
            for (int dy = 0; dy < 3; dy++)
                #pragma unroll
                for (int dx = 0; dx < 3; dx++)
                    acc += wd[dy * 3 + dx] * hb[(py + dy) * 18 + (px + dx)];
            g_qkv[(((size_t)b * C6 + o + q) * HH + (h0 + py)) * WW + (w0 + px)] = acc;
        }
        __syncthreads();
    }
}

// ---------------------------------------------------------------------------
// K2: per 64-col segment of one row: circular conv (8x8 on flat 64 chunk),
// channel LayerNorm (96), v*normed, 1x1 conv 96->48, write output.
// grid (4, 256, B), block 256, 2 CTAs/SM. Padded stride 68 => conflict-free.
// ---------------------------------------------------------------------------
__global__ void __launch_bounds__(256, 2)
fsas_k2(const float* __restrict__ gamma,
        const float* __restrict__ beta,
        const float* __restrict__ wout,
        const float* __restrict__ bout,
        float* __restrict__ out) {
    extern __shared__ float sm2[];
    float* qs   = sm2;                 // C2*ST  (reused for nv)
    float* ks   = qs + C2 * ST;        // C2*ST  (reused for circ-conv output)
    float* vs   = ks + C2 * ST;        // C2*ST
    float* wos  = vs + C2 * ST;        // CIN*C2
    float* red  = wos + CIN * C2;      // 512 (LN partials, 2x 4x64)
    float* mus  = red + 512;           // 64
    float* rss  = mus + 64;            // 64
    float* gms  = rss + 64;            // C2
    float* bts  = gms + C2;            // C2

    const int tid = threadIdx.x;
    const int b  = blockIdx.z;
    const int h  = blockIdx.y;
    const int w0 = blockIdx.x * 64;

    const size_t plane = (size_t)HH * WW;
    const size_t base  = (((size_t)b * C6) * HH + h) * WW + w0;

    // ---- load q,k,v tiles (float4) + weights -----------------------------
    for (int i4 = tid; i4 < C2 * 16; i4 += 256) {
        const int ch = i4 >> 4, z4 = (i4 & 15) << 2;
        const size_t off = base + (size_t)ch * plane + z4;
        *(float4*)&qs[ch * ST + z4] = *(const float4*)&g_qkv[off];
        *(float4*)&ks[ch * ST + z4] = *(const float4*)&g_qkv[off + (size_t)C2 * plane];
        *(float4*)&vs[ch * ST + z4] = *(const float4*)&g_qkv[off + (size_t)(2 * C2) * plane];
    }
    for (int i = tid; i < CIN * C2; i += 256) wos[i] = wout[i];
    if (tid < C2) { gms[tid] = gamma[tid]; bts[tid] = beta[tid]; }
    __syncthreads();

    // ---- 2D circular conv: thread (ch, 4 consecutive m rows) -------------
    float acc[4][8];
    const int cc = (tid < 96) ? tid : tid - 96;   // channel
    const int m0 = (tid < 96) ? 0 : 4;            // first m row
    if (tid < 192) {
        #pragma unroll
        for (int j = 0; j < 4; j++)
            #pragma unroll
            for (int n = 0; n < 8; n++) acc[j][n] = 0.0f;
        const float* qb = &qs[cc * ST];
        const float* kb = &ks[cc * ST];
        #pragma unroll
        for (int p = 0; p < 8; p++) {
            const float4 qa = *(const float4*)&qb[p * 8];
            const float4 qc = *(const float4*)&qb[p * 8 + 4];
            const float qv[8] = {qa.x,qa.y,qa.z,qa.w,qc.x,qc.y,qc.z,qc.w};
            #pragma unroll
            for (int j = 0; j < 4; j++) {
                const int kr = ((m0 + j - p) & 7) * 8;
                const float4 ka = *(const float4*)&kb[kr];
                const float4 kc = *(const float4*)&kb[kr + 4];
                const float kv[8] = {ka.x,ka.y,ka.z,ka.w,kc.x,kc.y,kc.z,kc.w};
                #pragma unroll
                for (int r = 0; r < 8; r++) {
                    #pragma unroll
                    for (int n = 0; n < 8; n++)
                        acc[j][n] += qv[r] * kv[(n - r) & 7];
                }
            }
        }
    }
    __syncthreads();           // all reads of qs/ks done
    if (tid < 192) {
        #pragma unroll
        for (int j = 0; j < 4; j++) {
            *(float4*)&ks[cc * ST + (m0 + j) * 8]     = *(float4*)&acc[j][0];
            *(float4*)&ks[cc * ST + (m0 + j) * 8 + 4] = *(float4*)&acc[j][4];
        }
    }
    __syncthreads();

    // ---- LayerNorm stats over 96 channels per pixel (4-way partials) -----
    {
        const int part = tid >> 6;      // 0..3
        const int z    = tid & 63;
        float sum = 0.f, sq = 0.f;
        #pragma unroll
        for (int ch = part; ch < C2; ch += 4) {
            const float v = ks[ch * ST + z];
            sum += v; sq += v * v;
        }
        red[part * 64 + z]       = sum;
        red[256 + part * 64 + z] = sq;
    }
    __syncthreads();
    if (tid < 64) {
        const float sum = red[tid] + red[64 + tid] + red[128 + tid] + red[192 + tid];
        const float sq  = red[256 + tid] + red[320 + tid] + red[384 + tid] + red[448 + tid];
        const float mu  = sum * (1.0f / C2);
        const float var = sq * (1.0f / C2) - mu * mu;
        mus[tid] = mu;
        rss[tid] = rsqrtf(var + 1e-5f);
    }
    __syncthreads();

    // ---- nv = v * normed, stored [ch][z] stride ST into qs ---------------
    for (int i = tid; i < C2 * 64; i += 256) {
        const int ch = i >> 6, z = i & 63;
        const float o_ = ks[ch * ST + z];
        const float nrm = (o_ - mus[z]) * rss[z] * gms[ch] + bts[ch];
        qs[ch * ST + z] = vs[ch * ST + z] * nrm;
    }
    __syncthreads();

    // ---- final 1x1 conv 96->48: thread = (q4, z), 12 co each -------------
    {
        const int q4 = tid >> 6;           // 0..3
        const int z  = tid & 63;
        float facc[12];
        #pragma unroll
        for (int c = 0; c < 12; c++) facc[c] = 0.f;
        #pragma unroll
        for (int cb = 0; cb < C2; cb += 4) {
            const float nv0 = qs[(cb + 0) * ST + z];
            const float nv1 = qs[(cb + 1) * ST + z];
            const float nv2 = qs[(cb + 2) * ST + z];
            const float nv3 = qs[(cb + 3) * ST + z];
            #pragma unroll
            for (int c = 0; c < 12; c++) {
                const float4 w4 = *(const float4*)&wos[(q4 * 12 + c) * C2 + cb];
                facc[c] += w4.x * nv0 + w4.y * nv1 + w4.z * nv2 + w4.w * nv3;
            }
        }
        const size_t obase = (((size_t)b * CIN + q4 * 12) * HH + h) * WW + w0 + z;
        #pragma unroll
        for (int c = 0; c < 12; c++)
            out[obase + (size_t)c * HH * WW] = facc[c] + bout[q4 * 12 + c];
    }
}

// ---------------------------------------------------------------------------
extern "C" void kernel_launch(void* const* d_in, const int* in_sizes, int n_in,
                              void* d_out, int out_size) {
    const float* x        = (const float*)d_in[0];
    const float* w_hidden = (const float*)d_in[1];
    const float* b_hidden = (const float*)d_in[2];
    const float* w_dw     = (const float*)d_in[3];
    const float* b_dw     = (const float*)d_in[4];
    const float* gamma    = (const float*)d_in[5];
    const float* beta     = (const float*)d_in[6];
    const float* w_out    = (const float*)d_in[7];
    const float* b_out    = (const float*)d_in[8];
    float* out = (float*)d_out;

    const int smem1 = (C6 * CIN + C6 * 9 + 2 * C6 + 4 * 324) * sizeof(float);
    const int smem2 = (3 * C2 * ST + CIN * C2 + 512 + 128 + 2 * C2) * sizeof(float);
    cudaFuncSetAttribute(fsas_k1, cudaFuncAttributeMaxDynamicSharedMemorySize, smem1);
    cudaFuncSetAttribute(fsas_k2, cudaFuncAttributeMaxDynamicSharedMemorySize, smem2);

    fsas_k1<<<dim3(16, 16, BATCH), 352, smem1>>>(x, w_hidden, b_hidden, w_dw, b_dw);
    fsas_k2<<<dim3(4, 256, BATCH), 256, smem2>>>(gamma, beta, w_out, b_out, out);
}

// round 10
// speedup vs baseline: 1.1858x; 1.1858x over previous
#include <cuda_runtime.h>
#include <cstddef>

#define BATCH 4
#define CIN   48
#define C6    288
#define C2    96
#define HH    256
#define WW    256
#define ST    68   // padded smem row stride (floats) for K2 tiles

// 302 MB scratch for qkv = dw3x3(conv1x1(x)); q=[0,96), k=[96,192), v=[192,288)
__device__ float g_qkv[(size_t)BATCH * C6 * HH * WW];

// ---- packed f32x2 helpers (sm_103a) ---------------------------------------
__device__ __forceinline__ unsigned long long pack2(float a, float b) {
    unsigned long long r;
    asm("mov.b64 %0, {%1, %2};" : "=l"(r) : "f"(a), "f"(b));
    return r;
}
__device__ __forceinline__ void unpack2(unsigned long long v, float& a, float& b) {
    asm("mov.b64 {%0, %1}, %2;" : "=f"(a), "=f"(b) : "l"(v));
}
__device__ __forceinline__ unsigned long long ffma2(unsigned long long a,
                                                    unsigned long long b,
                                                    unsigned long long c) {
    unsigned long long r;
    asm("fma.rn.f32x2 %0, %1, %2, %3;" : "=l"(r) : "l"(a), "l"(b), "l"(c));
    return r;
}

// ---------------------------------------------------------------------------
// K1: fused 1x1 conv (48->288) + depthwise 3x3 SAME -> g_qkv, FFMA2 packed.
// grid (16,16,B), block 352, 2 CTAs/SM. 8 output channels (4 pairs) per iter.
// ---------------------------------------------------------------------------
#define NOP (C6/2)   // 144 channel pairs

__global__ void __launch_bounds__(352, 2)
fsas_k1(const float* __restrict__ x,
        const float* __restrict__ w1,
        const float* __restrict__ b1,
        const float* __restrict__ wdw,
        const float* __restrict__ bdw) {
    extern __shared__ char smraw[];
    unsigned long long* w1p  = (unsigned long long*)smraw;  // [c][op] 48*144
    unsigned long long* wdwp = w1p + CIN * NOP;             // [op][j] 144*9
    unsigned long long* b1p  = wdwp + NOP * 9;              // 144
    unsigned long long* bdwp = b1p + NOP;                   // 144
    unsigned long long* hidp = bdwp + NOP;                  // [cp][324] 4*324

    const int tid = threadIdx.x;
    const int b  = blockIdx.z;
    const int h0 = blockIdx.y * 16;
    const int w0 = blockIdx.x * 16;

    // build packed weight tables
    for (int i = tid; i < CIN * NOP; i += 352) {
        const int c = i / NOP, op = i - c * NOP;
        w1p[i] = pack2(w1[(2 * op) * CIN + c], w1[(2 * op + 1) * CIN + c]);
    }
    for (int i = tid; i < NOP * 9; i += 352) {
        const int op = i / 9, j = i - op * 9;
        wdwp[i] = pack2(wdw[(2 * op) * 9 + j], wdw[(2 * op + 1) * 9 + j]);
    }
    for (int i = tid; i < NOP; i += 352) {
        b1p[i]  = pack2(b1[2 * i],  b1[2 * i + 1]);
        bdwp[i] = pack2(bdw[2 * i], bdw[2 * i + 1]);
    }

    // each thread owns one halo pixel (18x18 = 324) and register-caches x[ch]
    const int s  = tid;
    const int ty = s / 18, tx = s % 18;
    const int hh = h0 - 1 + ty;
    const int ww = w0 - 1 + tx;
    const bool inimg = (s < 324) && hh >= 0 && hh < HH && ww >= 0 && ww < WW;

    float xr[CIN];
    if (inimg) {
        const float* xp = x + ((size_t)b * CIN) * HH * WW + (size_t)hh * WW + ww;
        #pragma unroll
        for (int c = 0; c < CIN; c++) xr[c] = xp[(size_t)c * HH * WW];
    } else {
        #pragma unroll
        for (int c = 0; c < CIN; c++) xr[c] = 0.0f;
    }

    __syncthreads();

    for (int ob = 0; ob < 36; ob++) {           // channels 8*ob .. 8*ob+7
        if (s < 324) {
            unsigned long long acc0 = b1p[ob * 4 + 0];
            unsigned long long acc1 = b1p[ob * 4 + 1];
            unsigned long long acc2 = b1p[ob * 4 + 2];
            unsigned long long acc3 = b1p[ob * 4 + 3];
            #pragma unroll
            for (int c = 0; c < CIN; c++) {
                const unsigned long long xx = pack2(xr[c], xr[c]);
                const ulonglong2 p01 = *(const ulonglong2*)&w1p[c * NOP + ob * 4];
                const ulonglong2 p23 = *(const ulonglong2*)&w1p[c * NOP + ob * 4 + 2];
                acc0 = ffma2(p01.x, xx, acc0);
                acc1 = ffma2(p01.y, xx, acc1);
                acc2 = ffma2(p23.x, xx, acc2);
                acc3 = ffma2(p23.y, xx, acc3);
            }
            hidp[0 * 324 + s] = inimg ? acc0 : 0ULL;
            hidp[1 * 324 + s] = inimg ? acc1 : 0ULL;
            hidp[2 * 324 + s] = inimg ? acc2 : 0ULL;
            hidp[3 * 324 + s] = inimg ? acc3 : 0ULL;
        }
        __syncthreads();
        // depthwise 3x3: 256 pixels x 4 channel-pairs, all 352 threads
        for (int u = tid; u < 1024; u += 352) {
            const int cp  = u >> 8;
            const int pix = u & 255;
            const int py  = pix >> 4, px = pix & 15;
            const unsigned long long* wd = &wdwp[(ob * 4 + cp) * 9];
            const unsigned long long* hb = &hidp[cp * 324];
            unsigned long long a2 = bdwp[ob * 4 + cp];
            #pragma unroll
            for (int dy = 0; dy < 3; dy++)
                #pragma unroll
                for (int dx = 0; dx < 3; dx++)
                    a2 = ffma2(hb[(py + dy) * 18 + (px + dx)], wd[dy * 3 + dx], a2);
            float lo, hi;
            unpack2(a2, lo, hi);
            const int o = ob * 8 + cp * 2;
            const size_t base = (((size_t)b * C6 + o) * HH + (h0 + py)) * WW + (w0 + px);
            g_qkv[base] = lo;
            g_qkv[base + (size_t)HH * WW] = hi;
        }
        __syncthreads();
    }
}

// ---------------------------------------------------------------------------
// K2: per 64-col segment of one row: circular conv (8x8 on flat 64 chunk),
// channel LayerNorm (96), v*normed, 1x1 conv 96->48, write output.
// grid (4, 256, B), block 256, 2 CTAs/SM. Padded stride 68 => conflict-free.
// ---------------------------------------------------------------------------
__global__ void __launch_bounds__(256, 2)
fsas_k2(const float* __restrict__ gamma,
        const float* __restrict__ beta,
        const float* __restrict__ wout,
        const float* __restrict__ bout,
        float* __restrict__ out) {
    extern __shared__ float sm2[];
    float* qs   = sm2;                 // C2*ST  (reused for nv)
    float* ks   = qs + C2 * ST;        // C2*ST  (reused for circ-conv output)
    float* vs   = ks + C2 * ST;        // C2*ST
    float* wos  = vs + C2 * ST;        // CIN*C2
    float* red  = wos + CIN * C2;      // 512 (LN partials)
    float* mus  = red + 512;           // 64
    float* rss  = mus + 64;            // 64
    float* gms  = rss + 64;            // C2
    float* bts  = gms + C2;            // C2

    const int tid = threadIdx.x;
    const int b  = blockIdx.z;
    const int h  = blockIdx.y;
    const int w0 = blockIdx.x * 64;

    const size_t plane = (size_t)HH * WW;
    const size_t base  = (((size_t)b * C6) * HH + h) * WW + w0;

    // ---- load q,k,v tiles (float4) + weights -----------------------------
    for (int i4 = tid; i4 < C2 * 16; i4 += 256) {
        const int ch = i4 >> 4, z4 = (i4 & 15) << 2;
        const size_t off = base + (size_t)ch * plane + z4;
        *(float4*)&qs[ch * ST + z4] = *(const float4*)&g_qkv[off];
        *(float4*)&ks[ch * ST + z4] = *(const float4*)&g_qkv[off + (size_t)C2 * plane];
        *(float4*)&vs[ch * ST + z4] = *(const float4*)&g_qkv[off + (size_t)(2 * C2) * plane];
    }
    for (int i = tid; i < CIN * C2; i += 256) wos[i] = wout[i];
    if (tid < C2) { gms[tid] = gamma[tid]; bts[tid] = beta[tid]; }
    __syncthreads();

    // ---- 2D circular conv: thread (ch, 4 consecutive m rows) -------------
    float acc[4][8];
    const int cc = (tid < 96) ? tid : tid - 96;   // channel
    const int m0 = (tid < 96) ? 0 : 4;            // first m row
    if (tid < 192) {
        #pragma unroll
        for (int j = 0; j < 4; j++)
            #pragma unroll
            for (int n = 0; n < 8; n++) acc[j][n] = 0.0f;
        const float* qb = &qs[cc * ST];
        const float* kb = &ks[cc * ST];
        #pragma unroll
        for (int p = 0; p < 8; p++) {
            const float4 qa = *(const float4*)&qb[p * 8];
            const float4 qc = *(const float4*)&qb[p * 8 + 4];
            const float qv[8] = {qa.x,qa.y,qa.z,qa.w,qc.x,qc.y,qc.z,qc.w};
            #pragma unroll
            for (int j = 0; j < 4; j++) {
                const int kr = ((m0 + j - p) & 7) * 8;
                const float4 ka = *(const float4*)&kb[kr];
                const float4 kc = *(const float4*)&kb[kr + 4];
                const float kv[8] = {ka.x,ka.y,ka.z,ka.w,kc.x,kc.y,kc.z,kc.w};
                #pragma unroll
                for (int r = 0; r < 8; r++) {
                    #pragma unroll
                    for (int n = 0; n < 8; n++)
                        acc[j][n] += qv[r] * kv[(n - r) & 7];
                }
            }
        }
    }
    __syncthreads();           // all reads of qs/ks done
    if (tid < 192) {
        #pragma unroll
        for (int j = 0; j < 4; j++) {
            *(float4*)&ks[cc * ST + (m0 + j) * 8]     = *(float4*)&acc[j][0];
            *(float4*)&ks[cc * ST + (m0 + j) * 8 + 4] = *(float4*)&acc[j][4];
        }
    }
    __syncthreads();

    // ---- LayerNorm stats over 96 channels per pixel (4-way partials) -----
    {
        const int part = tid >> 6;      // 0..3
        const int z    = tid & 63;
        float sum = 0.f, sq = 0.f;
        #pragma unroll
        for (int ch = part; ch < C2; ch += 4) {
            const float v = ks[ch * ST + z];
            sum += v; sq += v * v;
        }
        red[part * 64 + z]       = sum;
        red[256 + part * 64 + z] = sq;
    }
    __syncthreads();
    if (tid < 64) {
        const float sum = red[tid] + red[64 + tid] + red[128 + tid] + red[192 + tid];
        const float sq  = red[256 + tid] + red[320 + tid] + red[384 + tid] + red[448 + tid];
        const float mu  = sum * (1.0f / C2);
        const float var = sq * (1.0f / C2) - mu * mu;
        mus[tid] = mu;
        rss[tid] = rsqrtf(var + 1e-5f);
    }
    __syncthreads();

    // ---- nv = v * normed, stored [ch][z] stride ST into qs ---------------
    for (int i = tid; i < C2 * 64; i += 256) {
        const int ch = i >> 6, z = i & 63;
        const float o_ = ks[ch * ST + z];
        const float nrm = (o_ - mus[z]) * rss[z] * gms[ch] + bts[ch];
        qs[ch * ST + z] = vs[ch * ST + z] * nrm;
    }
    __syncthreads();

    // ---- final 1x1 conv 96->48: thread = (q4, z), 12 co each -------------
    {
        const int q4 = tid >> 6;           // 0..3
        const int z  = tid & 63;
        float facc[12];
        #pragma unroll
        for (int c = 0; c < 12; c++) facc[c] = 0.f;
        #pragma unroll
        for (int cb = 0; cb < C2; cb += 4) {
            const float nv0 = qs[(cb + 0) * ST + z];
            const float nv1 = qs[(cb + 1) * ST + z];
            const float nv2 = qs[(cb + 2) * ST + z];
            const float nv3 = qs[(cb + 3) * ST + z];
            #pragma unroll
            for (int c = 0; c < 12; c++) {
                const float4 w4 = *(const float4*)&wos[(q4 * 12 + c) * C2 + cb];
                facc[c] += w4.x * nv0 + w4.y * nv1 + w4.z * nv2 + w4.w * nv3;
            }
        }
        const size_t obase = (((size_t)b * CIN + q4 * 12) * HH + h) * WW + w0 + z;
        #pragma unroll
        for (int c = 0; c < 12; c++)
            out[obase + (size_t)c * HH * WW] = facc[c] + bout[q4 * 12 + c];
    }
}

// ---------------------------------------------------------------------------
extern "C" void kernel_launch(void* const* d_in, const int* in_sizes, int n_in,
                              void* d_out, int out_size) {
    const float* x        = (const float*)d_in[0];
    const float* w_hidden = (const float*)d_in[1];
    const float* b_hidden = (const float*)d_in[2];
    const float* w_dw     = (const float*)d_in[3];
    const float* b_dw     = (const float*)d_in[4];
    const float* gamma    = (const float*)d_in[5];
    const float* beta     = (const float*)d_in[6];
    const float* w_out    = (const float*)d_in[7];
    const float* b_out    = (const float*)d_in[8];
    float* out = (float*)d_out;

    const int smem1 = (CIN * NOP + NOP * 9 + 2 * NOP + 4 * 324) * 8;   // 78336 B
    const int smem2 = (3 * C2 * ST + CIN * C2 + 512 + 128 + 2 * C2) * sizeof(float);
    cudaFuncSetAttribute(fsas_k1, cudaFuncAttributeMaxDynamicSharedMemorySize, smem1);
    cudaFuncSetAttribute(fsas_k2, cudaFuncAttributeMaxDynamicSharedMemorySize, smem2);

    fsas_k1<<<dim3(16, 16, BATCH), 352, smem1>>>(x, w_hidden, b_hidden, w_dw, b_dw);
    fsas_k2<<<dim3(4, 256, BATCH), 256, smem2>>>(gamma, beta, w_out, b_out, out);
}

// round 12
// speedup vs baseline: 1.2086x; 1.0192x over previous
#include <cuda_runtime.h>
#include <cstddef>

#define BATCH 4
#define CIN   48
#define C6    288
#define C2    96
#define HH    256
#define WW    256

typedef unsigned long long u64;

// 302 MB scratch for qkv = dw3x3(conv1x1(x)); q=[0,96), k=[96,192), v=[192,288)
__device__ float g_qkv[(size_t)BATCH * C6 * HH * WW];

// ---- packed f32x2 helpers (sm_103a) ---------------------------------------
__device__ __forceinline__ u64 pack2(float a, float b) {
    u64 r; asm("mov.b64 %0, {%1, %2};" : "=l"(r) : "f"(a), "f"(b)); return r;
}
__device__ __forceinline__ void unpack2(u64 v, float& a, float& b) {
    asm("mov.b64 {%0, %1}, %2;" : "=f"(a), "=f"(b) : "l"(v));
}
__device__ __forceinline__ u64 ffma2(u64 a, u64 b, u64 c) {
    u64 r; asm("fma.rn.f32x2 %0, %1, %2, %3;" : "=l"(r) : "l"(a), "l"(b), "l"(c)); return r;
}
__device__ __forceinline__ u64 add2(u64 a, u64 b) {
    u64 r; asm("add.rn.f32x2 %0, %1, %2;" : "=l"(r) : "l"(a), "l"(b)); return r;
}
__device__ __forceinline__ u64 mul2(u64 a, u64 b) {
    u64 r; asm("mul.rn.f32x2 %0, %1, %2;" : "=l"(r) : "l"(a), "l"(b)); return r;
}

// ---------------------------------------------------------------------------
// K1: fused 1x1 conv (48->288) + depthwise 3x3 SAME -> g_qkv, FFMA2 packed.
// grid (16,16,B), block 352, 2 CTAs/SM. 16 output channels (8 pairs) per iter.
// ---------------------------------------------------------------------------
#define NOP (C6/2)   // 144 channel pairs

__global__ void __launch_bounds__(352, 2)
fsas_k1(const float* __restrict__ x,
        const float* __restrict__ w1,
        const float* __restrict__ b1,
        const float* __restrict__ wdw,
        const float* __restrict__ bdw) {
    extern __shared__ char smraw[];
    u64* w1p  = (u64*)smraw;          // [c][op] 48*144
    u64* wdwp = w1p + CIN * NOP;      // [op][j] 144*9
    u64* b1p  = wdwp + NOP * 9;       // 144
    u64* bdwp = b1p + NOP;            // 144
    u64* hidp = bdwp + NOP;           // [cp][324] 8*324

    const int tid = threadIdx.x;
    const int b  = blockIdx.z;
    const int h0 = blockIdx.y * 16;
    const int w0 = blockIdx.x * 16;

    // build packed weight tables
    for (int i = tid; i < CIN * NOP; i += 352) {
        const int c = i / NOP, op = i - c * NOP;
        w1p[i] = pack2(w1[(2 * op) * CIN + c], w1[(2 * op + 1) * CIN + c]);
    }
    for (int i = tid; i < NOP * 9; i += 352) {
        const int op = i / 9, j = i - op * 9;
        wdwp[i] = pack2(wdw[(2 * op) * 9 + j], wdw[(2 * op + 1) * 9 + j]);
    }
    for (int i = tid; i < NOP; i += 352) {
        b1p[i]  = pack2(b1[2 * i],  b1[2 * i + 1]);
        bdwp[i] = pack2(bdw[2 * i], bdw[2 * i + 1]);
    }

    // each thread owns one halo pixel (18x18 = 324) and register-caches x[ch]
    const int s  = tid;
    const int ty = s / 18, tx = s % 18;
    const int hh = h0 - 1 + ty;
    const int ww = w0 - 1 + tx;
    const bool inimg = (s < 324) && hh >= 0 && hh < HH && ww >= 0 && ww < WW;

    float xr[CIN];
    if (inimg) {
        const float* xp = x + ((size_t)b * CIN) * HH * WW + (size_t)hh * WW + ww;
        #pragma unroll
        for (int c = 0; c < CIN; c++) xr[c] = xp[(size_t)c * HH * WW];
    } else {
        #pragma unroll
        for (int c = 0; c < CIN; c++) xr[c] = 0.0f;
    }

    __syncthreads();

    for (int ob = 0; ob < 18; ob++) {           // channels 16*ob .. 16*ob+15
        if (s < 324) {
            u64 acc[8];
            #pragma unroll
            for (int q = 0; q < 8; q++) acc[q] = b1p[ob * 8 + q];
            #pragma unroll
            for (int c = 0; c < CIN; c++) {
                const u64 xx = pack2(xr[c], xr[c]);
                const u64* wr = &w1p[c * NOP + ob * 8];
                #pragma unroll
                for (int k = 0; k < 4; k++) {
                    const ulonglong2 p2 = *(const ulonglong2*)&wr[2 * k];
                    acc[2 * k + 0] = ffma2(p2.x, xx, acc[2 * k + 0]);
                    acc[2 * k + 1] = ffma2(p2.y, xx, acc[2 * k + 1]);
                }
            }
            #pragma unroll
            for (int q = 0; q < 8; q++)
                hidp[q * 324 + s] = inimg ? acc[q] : 0ULL;
        }
        __syncthreads();
        // depthwise 3x3: 256 pixels x 8 channel-pairs, all 352 threads
        for (int u = tid; u < 2048; u += 352) {
            const int cp  = u >> 8;
            const int pix = u & 255;
            const int py  = pix >> 4, px = pix & 15;
            const u64* wd = &wdwp[(ob * 8 + cp) * 9];
            const u64* hb = &hidp[cp * 324];
            u64 a2 = bdwp[ob * 8 + cp];
            #pragma unroll
            for (int dy = 0; dy < 3; dy++)
                #pragma unroll
                for (int dx = 0; dx < 3; dx++)
                    a2 = ffma2(hb[(py + dy) * 18 + (px + dx)], wd[dy * 3 + dx], a2);
            float lo, hi;
            unpack2(a2, lo, hi);
            const int o = ob * 16 + cp * 2;
            const size_t base = (((size_t)b * C6 + o) * HH + (h0 + py)) * WW + (w0 + px);
            g_qkv[base] = lo;
            g_qkv[base + (size_t)HH * WW] = hi;
        }
        __syncthreads();
    }
}

// ---------------------------------------------------------------------------
// K2: packed-f32x2 version. Channel pairs (ch, ch+48). 48 packed rows/tensor.
// grid (4, 256, B), block 256, 2 CTAs/SM.
// ---------------------------------------------------------------------------
#define PST 66   // packed row stride in u64 (conflict-free, 16B-aligned)

__global__ void __launch_bounds__(256, 2)
fsas_k2(const float* __restrict__ gamma,
        const float* __restrict__ beta,
        const float* __restrict__ wout,
        const float* __restrict__ bout,
        float* __restrict__ out) {
    extern __shared__ char sm2raw[];
    u64* qs2  = (u64*)sm2raw;            // 48*PST (reused for nv)
    u64* ks2  = qs2 + 48 * PST;          // 48*PST (reused for circ-conv out)
    u64* vs2  = ks2 + 48 * PST;          // 48*PST
    u64* wos2 = vs2 + 48 * PST;          // [chp][co] 48*48
    u64* gb2  = wos2 + 48 * 48;          // gamma pairs 48 + beta pairs 48
    float* red = (float*)(gb2 + 96);     // 512
    float* mus = red + 512;              // 64
    float* rss = mus + 64;               // 64

    const int tid = threadIdx.x;
    const int b  = blockIdx.z;
    const int h  = blockIdx.y;
    const int w0 = blockIdx.x * 64;

    const size_t plane = (size_t)HH * WW;
    const size_t base  = (((size_t)b * C6) * HH + h) * WW + w0;

    // ---- load q,k,v tiles packed {ch, ch+48} -----------------------------
    for (int u = tid; u < 48 * 16; u += 256) {
        const int chp = u >> 4, z4 = (u & 15) << 2;
        const size_t olo = base + (size_t)chp * plane + z4;
        #pragma unroll
        for (int t = 0; t < 3; t++) {
            const size_t off = olo + (size_t)(t * C2) * plane;
            const float4 lo = *(const float4*)&g_qkv[off];
            const float4 hi = *(const float4*)&g_qkv[off + 48 * plane];
            u64* dst = (t == 0 ? qs2 : (t == 1 ? ks2 : vs2)) + chp * PST + z4;
            ulonglong2 p01, p23;
            p01.x = pack2(lo.x, hi.x); p01.y = pack2(lo.y, hi.y);
            p23.x = pack2(lo.z, hi.z); p23.y = pack2(lo.w, hi.w);
            *(ulonglong2*)&dst[0] = p01;
            *(ulonglong2*)&dst[2] = p23;
        }
    }
    for (int i = tid; i < 48 * 48; i += 256) {
        const int chp = i / 48, co = i - chp * 48;
        wos2[chp * 48 + co] = pack2(wout[co * C2 + chp], wout[co * C2 + chp + 48]);
    }
    if (tid < 48) {
        gb2[tid]      = pack2(gamma[tid], gamma[tid + 48]);
        gb2[48 + tid] = pack2(beta[tid],  beta[tid + 48]);
    }
    __syncthreads();

    // ---- 2D circular conv, packed: thread (chp, 2 m rows) ----------------
    u64 acc[2][8];
    const int chp = tid % 48;
    const int mq  = tid / 48;      // 0..3 valid (tid<192), m rows 2mq,2mq+1
    if (tid < 192) {
        #pragma unroll
        for (int j = 0; j < 2; j++)
            #pragma unroll
            for (int n = 0; n < 8; n++) acc[j][n] = 0ULL;
        const u64* qb = &qs2[chp * PST];
        const u64* kb = &ks2[chp * PST];
        #pragma unroll
        for (int p = 0; p < 8; p++) {
            u64 qv[8];
            #pragma unroll
            for (int k = 0; k < 4; k++) {
                const ulonglong2 t2 = *(const ulonglong2*)&qb[p * 8 + 2 * k];
                qv[2 * k] = t2.x; qv[2 * k + 1] = t2.y;
            }
            #pragma unroll
            for (int j = 0; j < 2; j++) {
                const int kr = ((2 * mq + j - p) & 7) * 8;
                u64 kv[8];
                #pragma unroll
                for (int k = 0; k < 4; k++) {
                    const ulonglong2 t2 = *(const ulonglong2*)&kb[kr + 2 * k];
                    kv[2 * k] = t2.x; kv[2 * k + 1] = t2.y;
                }
                #pragma unroll
                for (int r = 0; r < 8; r++) {
                    #pragma unroll
                    for (int n = 0; n < 8; n++)
                        acc[j][n] = ffma2(qv[r], kv[(n - r) & 7], acc[j][n]);
                }
            }
        }
    }
    __syncthreads();           // all reads of qs2/ks2 done
    if (tid < 192) {
        #pragma unroll
        for (int j = 0; j < 2; j++) {
            u64* dst = &ks2[chp * PST + (2 * mq + j) * 8];
            #pragma unroll
            for (int k = 0; k < 4; k++) {
                ulonglong2 t2; t2.x = acc[j][2 * k]; t2.y = acc[j][2 * k + 1];
                *(ulonglong2*)&dst[2 * k] = t2;
            }
        }
    }
    __syncthreads();

    // ---- LayerNorm stats: 4 partials over 12 packed rows each ------------
    {
        const int part = tid >> 6;      // 0..3
        const int z    = tid & 63;
        float sum = 0.f, sq = 0.f;
        #pragma unroll
        for (int c = 0; c < 12; c++) {
            float lo, hi;
            unpack2(ks2[(part * 12 + c) * PST + z], lo, hi);
            sum += lo + hi; sq += lo * lo + hi * hi;
        }
        red[part * 64 + z]       = sum;
        red[256 + part * 64 + z] = sq;
    }
    __syncthreads();
    if (tid < 64) {
        const float sum = red[tid] + red[64 + tid] + red[128 + tid] + red[192 + tid];
        const float sq  = red[256 + tid] + red[320 + tid] + red[384 + tid] + red[448 + tid];
        const float mu  = sum * (1.0f / C2);
        const float var = sq * (1.0f / C2) - mu * mu;
        mus[tid] = mu;
        rss[tid] = rsqrtf(var + 1e-5f);
    }
    __syncthreads();

    // ---- nv = v * normed (packed), into qs2 ------------------------------
    {
        const int z = tid & 63;
        const u64 nmu2 = pack2(-mus[z], -mus[z]);
        const u64 rs2  = pack2(rss[z], rss[z]);
        #pragma unroll
        for (int t = 0; t < 12; t++) {
            const int cp = (tid >> 6) + 4 * t;   // 0..47
            const u64 o2 = ks2[cp * PST + z];
            const u64 rsg = mul2(rs2, gb2[cp]);
            const u64 nrm = ffma2(add2(o2, nmu2), rsg, gb2[48 + cp]);
            qs2[cp * PST + z] = mul2(vs2[cp * PST + z], nrm);
        }
    }
    __syncthreads();

    // ---- final 1x1 conv 96->48, FFMA2: thread = (q4, z), 12 co -----------
    {
        const int q4 = tid >> 6;           // 0..3
        const int z  = tid & 63;
        u64 fac[12];
        #pragma unroll
        for (int c = 0; c < 12; c++) fac[c] = 0ULL;
        #pragma unroll
        for (int cp = 0; cp < 48; cp++) {
            const u64 nv2 = qs2[cp * PST + z];
            const u64* wr = &wos2[cp * 48 + q4 * 12];
            #pragma unroll
            for (int k = 0; k < 6; k++) {
                const ulonglong2 w2 = *(const ulonglong2*)&wr[2 * k];
                fac[2 * k]     = ffma2(nv2, w2.x, fac[2 * k]);
                fac[2 * k + 1] = ffma2(nv2, w2.y, fac[2 * k + 1]);
            }
        }
        const size_t obase = (((size_t)b * CIN + q4 * 12) * HH + h) * WW + w0 + z;
        #pragma unroll
        for (int c = 0; c < 12; c++) {
            float lo, hi;
            unpack2(fac[c], lo, hi);
            out[obase + (size_t)c * HH * WW] = lo + hi + bout[q4 * 12 + c];
        }
    }
}

// ---------------------------------------------------------------------------
extern "C" void kernel_launch(void* const* d_in, const int* in_sizes, int n_in,
                              void* d_out, int out_size) {
    const float* x        = (const float*)d_in[0];
    const float* w_hidden = (const float*)d_in[1];
    const float* b_hidden = (const float*)d_in[2];
    const float* w_dw     = (const float*)d_in[3];
    const float* b_dw     = (const float*)d_in[4];
    const float* gamma    = (const float*)d_in[5];
    const float* beta     = (const float*)d_in[6];
    const float* w_out    = (const float*)d_in[7];
    const float* b_out    = (const float*)d_in[8];
    float* out = (float*)d_out;

    const int smem1 = (CIN * NOP + NOP * 9 + 2 * NOP + 8 * 324) * 8;           // 88704 B
    const int smem2 = (3 * 48 * PST + 48 * 48 + 96) * 8 + (512 + 128) * 4;     // ~97.8 KB
    cudaFuncSetAttribute(fsas_k1, cudaFuncAttributeMaxDynamicSharedMemorySize, smem1);
    cudaFuncSetAttribute(fsas_k2, cudaFuncAttributeMaxDynamicSharedMemorySize, smem2);

    fsas_k1<<<dim3(16, 16, BATCH), 352, smem1>>>(x, w_hidden, b_hidden, w_dw, b_dw);
    fsas_k2<<<dim3(4, 256, BATCH), 256, smem2>>>(gamma, beta, w_out, b_out, out);
}